// round 12
// baseline (speedup 1.0000x reference)
#include <cuda_runtime.h>
#include <cuda_bf16.h>

// ---------------------------------------------------------------------------
// YOLO loss reduction: 1024 x 28 x 28 cells -> 5 scalars.
// Round 11: bulk-TMA streaming.  The LDG path caps at ~64-128 outstanding
// lines/SM (~4.1 TB/s chip-wide, the invariant wall of R3-R10).  cp.async.bulk
// is tracked by the TMA engine instead -> 2 CTAs/SM x 2 x 55KB buffers in
// flight.  1568 blocks x 2 tiles, double buffered, mbarrier complete_tx.
// Tail: per-block float4 partial + one u32 ticket; last block finalizes.
// ---------------------------------------------------------------------------

#define NTILES   3136        // 802816 / 256 cells
#define GRID     1568        // 2 tiles per block
#define TPB      256
#define INV_S    0.0357142857142857f   // 1/28
#define N_BATCH  1024.0

// per-buffer layout (bytes): pred 30720 | tcls 20480 | tbox 4096 | mask 1024
#define OFF_TCLS 30720
#define OFF_TBOX 51200
#define OFF_MASK 55296
#define BUF_BYTES 56320
#define SMEM_DYN (2 * BUF_BYTES + 16)   // + two mbarriers

__device__ __align__(16) float4 g_part[GRID];   // per-block partials
__device__ unsigned int g_count;                // ticket (zero-init)

__device__ __forceinline__ void mbar_init(unsigned mbar, unsigned count) {
    asm volatile("mbarrier.init.shared.b64 [%0], %1;"
                 :: "r"(mbar), "r"(count) : "memory");
}
__device__ __forceinline__ void mbar_expect_tx(unsigned mbar, unsigned bytes) {
    asm volatile("mbarrier.arrive.expect_tx.shared.b64 _, [%0], %1;"
                 :: "r"(mbar), "r"(bytes) : "memory");
}
__device__ __forceinline__ void bulk_g2s(unsigned dst, const void* src,
                                         unsigned bytes, unsigned mbar) {
    asm volatile("cp.async.bulk.shared::cta.global.mbarrier::complete_tx::bytes "
                 "[%0], [%1], %2, [%3];"
                 :: "r"(dst), "l"(src), "r"(bytes), "r"(mbar) : "memory");
}
__device__ __forceinline__ void mbar_wait(unsigned mbar, unsigned parity) {
    asm volatile(
        "{\n\t.reg .pred P;\n"
        "W%=:\n\t"
        "mbarrier.try_wait.parity.acquire.cta.shared::cta.b64 P, [%0], %1, 0x989680;\n\t"
        "@P bra D%=;\n\t"
        "bra W%=;\n"
        "D%=:\n\t}"
        :: "r"(mbar), "r"(parity) : "memory");
}

// per-tile compute from a shared buffer; accumulates into a4[4]
__device__ __forceinline__ void tile_compute(const char* buf, int tid, float* a4) {
    const float*    sp   = (const float*)(buf);
    const float4*   sc4  = (const float4*)(buf + OFF_TCLS);
    const float4*   sbx  = (const float4*)(buf + OFF_TBOX);
    const unsigned* smsk = (const unsigned*)(buf + OFF_MASK);

    // class loss: e4 in [0,1280): cl = e4/5, ch = 4*(e4%5)
    float acc_cls = 0.0f;
    #pragma unroll
    for (int j = 0; j < 5; j++) {
        int e4 = tid + TPB * j;
        int cl = e4 / 5;
        int ch = 4 * (e4 - cl * 5);
        const float* pc = sp + cl * 30 + 10 + ch;
        float mm = (smsk[cl] != 0u) ? 1.0f : 0.0f;
        float4 t = sc4[e4];
        float d0 = pc[0] - t.x;
        float d1 = pc[1] - t.y;
        float d2 = pc[2] - t.z;
        float d3 = pc[3] - t.w;
        acc_cls += mm * (d0 * d0 + d1 * d1 + d2 * d2 + d3 * d3);
    }

    // per-cell box terms
    const float* p   = sp + tid * 30;
    const float4 tbv = sbx[tid];
    const float  m   = (smsk[tid] != 0u) ? 1.0f : 0.0f;

    float tcx = tbv.x * INV_S, tcy = tbv.y * INV_S;
    float thw = 0.5f * tbv.z, thh = 0.5f * tbv.w;
    float tbx1 = tcx - thw, tby1 = tcy - thh;
    float tbx2 = tcx + thw, tby2 = tcy + thh;
    float ta = (tbx2 - tbx1) * (tby2 - tby1);

    float bx1[2], by1[2], bx2[2], by2[2], iou[2], cf[2];
    #pragma unroll
    for (int b = 0; b < 2; b++) {
        float x = p[5 * b + 0], y = p[5 * b + 1];
        float w = p[5 * b + 2], h = p[5 * b + 3];
        cf[b] = p[5 * b + 4];
        float cx = x * INV_S, cy = y * INV_S;
        float hw = 0.5f * w, hh = 0.5f * h;
        bx1[b] = cx - hw; by1[b] = cy - hh;
        bx2[b] = cx + hw; by2[b] = cy + hh;
        float ltx = fmaxf(bx1[b], tbx1), lty = fmaxf(by1[b], tby1);
        float rbx = fminf(bx2[b], tbx2), rby = fminf(by2[b], tby2);
        float wi = fmaxf(rbx - ltx, 0.0f), hi = fmaxf(rby - lty, 0.0f);
        float inter = wi * hi;
        float a1 = (bx2[b] - bx1[b]) * (by2[b] - by1[b]);
        iou[b] = inter / (a1 + ta - inter);
    }

    int best = (iou[1] > iou[0]) ? 1 : 0;   // first max wins (jnp.argmax)
    float biou = iou[best];
    float bbx1 = bx1[best], bby1 = by1[best];
    float bbx2 = bx2[best], bby2 = by2[best];
    float bconf = cf[best];
    if (!(biou > 0.0f)) {
        bbx1 = bby1 = bbx2 = bby2 = 0.0f;
        bconf = 0.0f; biou = 0.0f;
    }

    float dx = bbx1 - tbx1, dy = bby1 - tby1;
    float lxy = dx * dx + dy * dy;
    float s1 = (bbx2 > 0.0f) ? sqrtf(bbx2) : 0.0f;
    float s2 = (bby2 > 0.0f) ? sqrtf(bby2) : 0.0f;
    float t1 = (tbx2 > 0.0f) ? sqrtf(tbx2) : 0.0f;
    float t2 = (tby2 > 0.0f) ? sqrtf(tby2) : 0.0f;
    float dw = s1 - t1, dh = s2 - t2;
    float lwh = dw * dw + dh * dh;

    a4[0] += acc_cls;
    a4[1] += (1.0f - m) * (cf[0] * cf[0] + cf[1] * cf[1]);
    a4[2] += m * (lxy + lwh);
    float dc = bconf - biou;
    a4[3] += m * dc * dc;
}

__global__ void __launch_bounds__(TPB) yolo_main_k(
    const float* __restrict__ pred,   // [802816, 30]
    const float* __restrict__ tbox,   // [802816, 4]
    const float* __restrict__ tcls,   // [802816, 20]
    const unsigned int* __restrict__ mask,  // [802816] words, truth <=> w != 0
    float*       __restrict__ out)
{
    extern __shared__ __align__(128) char dynsmem[];
    __shared__ float red[8][4];
    __shared__ unsigned int s_ticket;

    const int tid = threadIdx.x;
    const int t0  = blockIdx.x * 2;        // first tile
    const int t1  = t0 + 1;                // second tile

    char* buf0 = dynsmem;
    char* buf1 = dynsmem + BUF_BYTES;
    const unsigned sbase = (unsigned)__cvta_generic_to_shared(dynsmem);
    const unsigned mbar0 = sbase + 2 * BUF_BYTES;
    const unsigned mbar1 = mbar0 + 8;

    if (tid == 0) { mbar_init(mbar0, 1); mbar_init(mbar1, 1); }
    __syncthreads();

    if (tid == 0) {
        // tile t0 -> buf0
        mbar_expect_tx(mbar0, BUF_BYTES);
        bulk_g2s(sbase,                       pred + (size_t)t0 * 7680, 30720, mbar0);
        bulk_g2s(sbase + OFF_TCLS,            tcls + (size_t)t0 * 5120, 20480, mbar0);
        bulk_g2s(sbase + OFF_TBOX,            tbox + (size_t)t0 * 1024,  4096, mbar0);
        bulk_g2s(sbase + OFF_MASK,            mask + (size_t)t0 * 256,   1024, mbar0);
        // tile t1 -> buf1 (in flight concurrently)
        mbar_expect_tx(mbar1, BUF_BYTES);
        bulk_g2s(sbase + BUF_BYTES,            pred + (size_t)t1 * 7680, 30720, mbar1);
        bulk_g2s(sbase + BUF_BYTES + OFF_TCLS, tcls + (size_t)t1 * 5120, 20480, mbar1);
        bulk_g2s(sbase + BUF_BYTES + OFF_TBOX, tbox + (size_t)t1 * 1024,  4096, mbar1);
        bulk_g2s(sbase + BUF_BYTES + OFF_MASK, mask + (size_t)t1 * 256,   1024, mbar1);
    }

    float a4[4] = { 0.f, 0.f, 0.f, 0.f };   // cls, nbj, reg, cobj

    mbar_wait(mbar0, 0);
    tile_compute(buf0, tid, a4);

    mbar_wait(mbar1, 0);
    tile_compute(buf1, tid, a4);

    // ---- block reduction: warp shuffle -> shared -> ONE plain store --------
    #pragma unroll
    for (int j = 0; j < 4; j++) {
        #pragma unroll
        for (int o = 16; o; o >>= 1)
            a4[j] += __shfl_down_sync(0xffffffffu, a4[j], o);
    }
    int warp = tid >> 5, lane = tid & 31;
    if (lane == 0) {
        red[warp][0] = a4[0]; red[warp][1] = a4[1];
        red[warp][2] = a4[2]; red[warp][3] = a4[3];
    }
    __syncthreads();
    if (tid == 0) {
        float s0 = 0.f, s1 = 0.f, s2 = 0.f, s3 = 0.f;
        #pragma unroll
        for (int w = 0; w < 8; w++) {
            s0 += red[w][0]; s1 += red[w][1];
            s2 += red[w][2]; s3 += red[w][3];
        }
        g_part[blockIdx.x] = make_float4(s0, s1, s2, s3);

        __threadfence();
        s_ticket = atomicAdd(&g_count, 1u);
    }
    __syncthreads();

    // ---- last block: reduce all partials and finalize -----------------------
    if (s_ticket == GRID - 1) {
        __threadfence();   // acquire: observe all partials
        __shared__ double rd[8][4];

        double d0 = 0.0, d1 = 0.0, d2 = 0.0, d3 = 0.0;
        for (int i = tid; i < GRID; i += TPB) {
            float4 v = g_part[i];
            d0 += (double)v.x; d1 += (double)v.y;
            d2 += (double)v.z; d3 += (double)v.w;
        }
        #pragma unroll
        for (int o = 16; o; o >>= 1) {
            d0 += __shfl_down_sync(0xffffffffu, d0, o);
            d1 += __shfl_down_sync(0xffffffffu, d1, o);
            d2 += __shfl_down_sync(0xffffffffu, d2, o);
            d3 += __shfl_down_sync(0xffffffffu, d3, o);
        }
        if (lane == 0) { rd[warp][0] = d0; rd[warp][1] = d1; rd[warp][2] = d2; rd[warp][3] = d3; }
        __syncthreads();
        if (tid == 0) {
            double cls = 0.0, nbj = 0.0, reg = 0.0, cobj = 0.0;
            #pragma unroll
            for (int w = 0; w < 8; w++) {
                cls += rd[w][0]; nbj += rd[w][1];
                reg += rd[w][2]; cobj += rd[w][3];
            }
            double cls_l  = 2.0 * cls / N_BATCH;
            double nbj_l  = 0.5 * nbj / N_BATCH;
            double reg_l  = 5.0 * reg / N_BATCH;
            double cobj_l = cobj / N_BATCH;
            out[0] = (float)(cls_l + nbj_l + reg_l + cobj_l);
            out[1] = (float)reg_l;
            out[2] = (float)cobj_l;
            out[3] = (float)nbj_l;
            out[4] = (float)cls_l;
            atomicExch(&g_count, 0u);   // self-reset for next graph replay
        }
    }
}

extern "C" void kernel_launch(void* const* d_in, const int* in_sizes, int n_in,
                              void* d_out, int out_size) {
    const float* pred = nullptr;
    const float* tbox = nullptr;
    const float* tcls = nullptr;
    const void*  mask = nullptr;
    for (int i = 0; i < n_in; i++) {
        switch (in_sizes[i]) {
            case 24084480: pred = (const float*)d_in[i]; break;  // 802816*30
            case 16056320: tcls = (const float*)d_in[i]; break;  // 802816*20
            case 3211264:  tbox = (const float*)d_in[i]; break;  // 802816*4
            case 802816:   mask = d_in[i];               break;  // 802816
        }
    }
    static int attr_done = 0;
    if (!attr_done) {
        cudaFuncSetAttribute(yolo_main_k,
                             cudaFuncAttributeMaxDynamicSharedMemorySize, SMEM_DYN);
        attr_done = 1;
    }
    yolo_main_k<<<GRID, TPB, SMEM_DYN>>>(pred, tbox, tcls,
                                         (const unsigned int*)mask, (float*)d_out);
}

// round 13
// speedup vs baseline: 1.0457x; 1.0457x over previous
#include <cuda_runtime.h>
#include <cuda_bf16.h>

// ---------------------------------------------------------------------------
// YOLO loss reduction: 1024 x 28 x 28 cells -> 5 scalars.
// Round 13: R3 structure + cp.async.bulk.prefetch.L2 (fire-and-forget) for
// tile bid+512.  Consumption LDGs then hit L2 (~250cyc) instead of DRAM
// (~600cyc), testing the outstanding-miss-cap theory of the 4.1 TB/s wall.
// ---------------------------------------------------------------------------

#define NTILES    3136       // 802816 / 256
#define TPB       256
#define PREF_DIST 512        // tiles ahead (~28 MB rolling L2 window)
#define INV_S     0.0357142857142857f   // 1/28
#define N_BATCH   1024.0

__device__ double       g_acc[4];   // cls, nbj, reg, cobj raw sums (zero-init)
__device__ unsigned int g_count;    // finished-block ticket (zero-init)

__device__ __forceinline__ void l2_prefetch(const void* p, unsigned bytes) {
    asm volatile("cp.async.bulk.prefetch.L2.global [%0], %1;"
                 :: "l"(p), "r"(bytes) : "memory");
}

__global__ void __launch_bounds__(TPB) yolo_main_k(
    const float* __restrict__ pred,   // [802816, 30]
    const float* __restrict__ tbox,   // [802816, 4]
    const float* __restrict__ tcls,   // [802816, 20]
    const unsigned int* __restrict__ mask,  // [802816] words, truth <=> w != 0
    float*       __restrict__ out)
{
    __shared__ __align__(16) float sp[TPB * 30];   // staged pred tile
    __shared__ float smk[TPB];                     // mask as float
    __shared__ float red[8][4];

    const int tid   = threadIdx.x;
    const int cell0 = blockIdx.x * TPB;

    // --- L2 prefetch for the tile PREF_DIST ahead (fire-and-forget) ---------
    if (tid == 0) {
        int tp = blockIdx.x + PREF_DIST;
        if (tp < NTILES) {
            l2_prefetch(pred + (size_t)tp * 7680, 30720);
            l2_prefetch(tcls + (size_t)tp * 5120, 20480);
            l2_prefetch(tbox + (size_t)tp * 1024,  4096);
            l2_prefetch(mask + (size_t)tp * 256,   1024);
        }
    }

    // --- pred staging: coalesced float4 LDG -> STS (1920 float4) ------------
    {
        const float4* p4  = (const float4*)(pred + (size_t)cell0 * 30);
        float4*       sp4 = (float4*)sp;
        #pragma unroll
        for (int i = tid; i < 1920; i += TPB) sp4[i] = p4[i];
    }

    // --- tcls prefetch into registers (in flight with pred staging) ---------
    float4 tc[5];
    {
        const float4* tcg4 = (const float4*)(tcls + (size_t)cell0 * 20);
        #pragma unroll
        for (int j = 0; j < 5; j++) tc[j] = tcg4[tid + TPB * j];
    }

    // --- tbox + mask: direct coalesced loads --------------------------------
    const float4 tbv = ((const float4*)tbox)[cell0 + tid];
    smk[tid] = (mask[cell0 + tid] != 0u) ? 1.0f : 0.0f;

    __syncthreads();   // sp + smk visible

    // --- class loss: registers (tc) vs shared pred --------------------------
    // e4 in [0,1280): cl = e4/5, ch = 4*(e4%5); float4 never crosses a cell.
    float acc_cls = 0.0f;
    #pragma unroll
    for (int j = 0; j < 5; j++) {
        int e4 = tid + TPB * j;
        int cl = e4 / 5;
        int ch = 4 * (e4 - cl * 5);
        const float* pc = sp + cl * 30 + 10 + ch;
        float mm = smk[cl];
        float d0 = pc[0] - tc[j].x;
        float d1 = pc[1] - tc[j].y;
        float d2 = pc[2] - tc[j].z;
        float d3 = pc[3] - tc[j].w;
        acc_cls += mm * (d0 * d0 + d1 * d1 + d2 * d2 + d3 * d3);
    }

    // --- per-cell box terms --------------------------------------------------
    const float* p = sp + tid * 30;
    const float  m = smk[tid];

    float tcx = tbv.x * INV_S, tcy = tbv.y * INV_S;
    float thw = 0.5f * tbv.z, thh = 0.5f * tbv.w;
    float tbx1 = tcx - thw, tby1 = tcy - thh;
    float tbx2 = tcx + thw, tby2 = tcy + thh;
    float ta = (tbx2 - tbx1) * (tby2 - tby1);

    float bx1[2], by1[2], bx2[2], by2[2], iou[2], cf[2];
    #pragma unroll
    for (int b = 0; b < 2; b++) {
        float x = p[5 * b + 0], y = p[5 * b + 1];
        float w = p[5 * b + 2], h = p[5 * b + 3];
        cf[b] = p[5 * b + 4];
        float cx = x * INV_S, cy = y * INV_S;
        float hw = 0.5f * w, hh = 0.5f * h;
        bx1[b] = cx - hw; by1[b] = cy - hh;
        bx2[b] = cx + hw; by2[b] = cy + hh;
        float ltx = fmaxf(bx1[b], tbx1), lty = fmaxf(by1[b], tby1);
        float rbx = fminf(bx2[b], tbx2), rby = fminf(by2[b], tby2);
        float wi = fmaxf(rbx - ltx, 0.0f), hi = fmaxf(rby - lty, 0.0f);
        float inter = wi * hi;
        float a1 = (bx2[b] - bx1[b]) * (by2[b] - by1[b]);
        iou[b] = inter / (a1 + ta - inter);
    }

    int best = (iou[1] > iou[0]) ? 1 : 0;   // first max wins (jnp.argmax)
    float biou = iou[best];
    float bbx1 = bx1[best], bby1 = by1[best];
    float bbx2 = bx2[best], bby2 = by2[best];
    float bconf = cf[best];
    if (!(biou > 0.0f)) {
        bbx1 = bby1 = bbx2 = bby2 = 0.0f;
        bconf = 0.0f; biou = 0.0f;
    }

    float dx = bbx1 - tbx1, dy = bby1 - tby1;
    float lxy = dx * dx + dy * dy;
    float s1 = (bbx2 > 0.0f) ? sqrtf(bbx2) : 0.0f;
    float s2 = (bby2 > 0.0f) ? sqrtf(bby2) : 0.0f;
    float t1 = (tbx2 > 0.0f) ? sqrtf(tbx2) : 0.0f;
    float t2 = (tby2 > 0.0f) ? sqrtf(tby2) : 0.0f;
    float dw = s1 - t1, dh = s2 - t2;
    float lwh = dw * dw + dh * dh;

    float acc_reg  = m * (lxy + lwh);
    float dc       = bconf - biou;
    float acc_cobj = m * dc * dc;
    float acc_nbj  = (1.0f - m) * (cf[0] * cf[0] + cf[1] * cf[1]);

    // --- reduction: warp shuffle -> shared -> double atomics ----------------
    float a4[4] = { acc_cls, acc_nbj, acc_reg, acc_cobj };
    #pragma unroll
    for (int j = 0; j < 4; j++) {
        #pragma unroll
        for (int o = 16; o; o >>= 1)
            a4[j] += __shfl_down_sync(0xffffffffu, a4[j], o);
    }
    int warp = tid >> 5, lane = tid & 31;
    if (lane == 0) {
        red[warp][0] = a4[0]; red[warp][1] = a4[1];
        red[warp][2] = a4[2]; red[warp][3] = a4[3];
    }
    __syncthreads();
    if (tid == 0) {
        double s[4] = {0.0, 0.0, 0.0, 0.0};
        #pragma unroll
        for (int w = 0; w < 8; w++)
            for (int j = 0; j < 4; j++) s[j] += (double)red[w][j];
        atomicAdd(&g_acc[0], s[0]);
        atomicAdd(&g_acc[1], s[1]);
        atomicAdd(&g_acc[2], s[2]);
        atomicAdd(&g_acc[3], s[3]);

        __threadfence();
        unsigned int ticket = atomicAdd(&g_count, 1u);
        if (ticket == NTILES - 1) {
            double cls  = atomicAdd(&g_acc[0], 0.0);
            double nbj  = atomicAdd(&g_acc[1], 0.0);
            double reg  = atomicAdd(&g_acc[2], 0.0);
            double cobj = atomicAdd(&g_acc[3], 0.0);
            double cls_l  = 2.0 * cls / N_BATCH;
            double nbj_l  = 0.5 * nbj / N_BATCH;
            double reg_l  = 5.0 * reg / N_BATCH;
            double cobj_l = cobj / N_BATCH;
            out[0] = (float)(cls_l + nbj_l + reg_l + cobj_l);
            out[1] = (float)reg_l;
            out[2] = (float)cobj_l;
            out[3] = (float)nbj_l;
            out[4] = (float)cls_l;
            // self-reset for the next graph replay
            atomicExch((unsigned long long*)&g_acc[0], 0ull);
            atomicExch((unsigned long long*)&g_acc[1], 0ull);
            atomicExch((unsigned long long*)&g_acc[2], 0ull);
            atomicExch((unsigned long long*)&g_acc[3], 0ull);
            atomicExch(&g_count, 0u);
        }
    }
}

extern "C" void kernel_launch(void* const* d_in, const int* in_sizes, int n_in,
                              void* d_out, int out_size) {
    const float* pred = nullptr;
    const float* tbox = nullptr;
    const float* tcls = nullptr;
    const void*  mask = nullptr;
    for (int i = 0; i < n_in; i++) {
        switch (in_sizes[i]) {
            case 24084480: pred = (const float*)d_in[i]; break;  // 802816*30
            case 16056320: tcls = (const float*)d_in[i]; break;  // 802816*20
            case 3211264:  tbox = (const float*)d_in[i]; break;  // 802816*4
            case 802816:   mask = d_in[i];               break;  // 802816
        }
    }
    yolo_main_k<<<NTILES, TPB>>>(pred, tbox, tcls,
                                 (const unsigned int*)mask, (float*)d_out);
}